// round 2
// baseline (speedup 1.0000x reference)
#include <cuda_runtime.h>

#define BB 32
#define SS 512
#define HH 256
#define NB 256
#define TT 4096   // MAX_LEN

// scratch (no allocations allowed)
__device__ float g_combined[BB * SS * HH];   // 16 MB
__device__ int   g_cum[BB * SS];

// searchsorted(linspace(vmin,vmax,NB), v, side='left'), clipped to [0, NB-1].
// Post-clip v <= vmax = b[NB-1], so answer is in [0, NB-1]: 256 candidates,
// exactly 8 halving iterations.
__device__ __forceinline__ int quantize_bin(float v, float vmin, float vmax) {
    v = fminf(fmaxf(v, vmin), vmax);
    float step = __fdiv_rn(__fsub_rn(vmax, vmin), (float)(NB - 1));
    int lo = 0, hi = NB - 1;      // first i with b_i >= v
    #pragma unroll
    for (int it = 0; it < 8; ++it) {
        int mid = (lo + hi) >> 1;
        float b = __fadd_rn(__fmul_rn((float)mid, step), vmin);
        if (b >= v) hi = mid; else lo = mid + 1;
    }
    return lo;
}

// one block per batch row: inclusive scan of clamped rounded durations
__global__ void cumsum_kernel(const float* __restrict__ dur) {
    __shared__ int s[SS];
    int b = blockIdx.x;
    int i = threadIdx.x;
    int d = max((int)rintf(dur[b * SS + i]), 1);  // rintf = round half to even (jnp.round)
    s[i] = d;
    __syncthreads();
    #pragma unroll
    for (int off = 1; off < SS; off <<= 1) {
        int v = (i >= off) ? s[i - off] : 0;
        __syncthreads();
        s[i] += v;
        __syncthreads();
    }
    g_cum[b * SS + i] = s[i];
}

// one block per token (b,s): combined = enc + ptab[pbin] + etab[ebin]
__global__ void combine_kernel(const float* __restrict__ enc,
                               const float* __restrict__ pitch,
                               const float* __restrict__ energy,
                               const float* __restrict__ ptab,
                               const float* __restrict__ etab) {
    int row = blockIdx.x;                 // b*SS + s
    __shared__ int pb, eb;
    if (threadIdx.x == 0) {
        pb = quantize_bin(pitch[row],  50.0f, 400.0f);
        eb = quantize_bin(energy[row],  0.0f,   1.0f);
    }
    __syncthreads();
    int lane = threadIdx.x;               // 64 threads, float4 each
    const float4* e4 = (const float4*)(enc + (size_t)row * HH);
    const float4* p4 = (const float4*)(ptab + (size_t)pb * HH);
    const float4* q4 = (const float4*)(etab + (size_t)eb * HH);
    float4 a = e4[lane], p = p4[lane], q = q4[lane];
    float4 r;
    r.x = a.x + p.x + q.x;
    r.y = a.y + p.y + q.y;
    r.z = a.z + p.z + q.z;
    r.w = a.w + p.w + q.w;
    ((float4*)g_combined)[(size_t)row * (HH / 4) + lane] = r;
}

// grid (TT/FPB, BB), block 256: each 8-thread group handles one output frame
#define FPB 32
__global__ void regulate_kernel(float* __restrict__ out) {
    __shared__ int cum[SS];
    int b = blockIdx.y;
    for (int i = threadIdx.x; i < SS; i += blockDim.x)
        cum[i] = g_cum[b * SS + i];
    __syncthreads();

    int total = cum[SS - 1];
    int frame_local = threadIdx.x >> 3;   // 0..31
    int lane        = threadIdx.x & 7;    // 0..7
    int t = blockIdx.x * FPB + frame_local;

    float4* dst = (float4*)out + ((size_t)b * TT + t) * (HH / 4);

    if (t >= total) {
        float4 z = make_float4(0.f, 0.f, 0.f, 0.f);
        #pragma unroll
        for (int j = 0; j < 8; ++j)
            dst[j * 8 + lane] = z;
        return;
    }

    // side='right': first j with cum[j] > t. t < total = cum[SS-1] guarantees
    // the answer is in [0, SS-1]: 512 candidates, exactly 9 halving iterations.
    int lo = 0, hi = SS - 1;
    #pragma unroll
    for (int it = 0; it < 9; ++it) {
        int mid = (lo + hi) >> 1;
        if (cum[mid] > t) hi = mid; else lo = mid + 1;
    }
    int idx = lo;

    const float4* src = (const float4*)g_combined + ((size_t)b * SS + idx) * (HH / 4);
    #pragma unroll
    for (int j = 0; j < 8; ++j)
        dst[j * 8 + lane] = src[j * 8 + lane];
}

extern "C" void kernel_launch(void* const* d_in, const int* in_sizes, int n_in,
                              void* d_out, int out_size) {
    const float* enc    = (const float*)d_in[0];
    const float* pitch  = (const float*)d_in[1];
    const float* energy = (const float*)d_in[2];
    const float* dur    = (const float*)d_in[3];
    const float* ptab   = (const float*)d_in[4];
    const float* etab   = (const float*)d_in[5];
    float* out = (float*)d_out;

    cumsum_kernel<<<BB, SS>>>(dur);
    combine_kernel<<<BB * SS, 64>>>(enc, pitch, energy, ptab, etab);
    regulate_kernel<<<dim3(TT / FPB, BB), 256>>>(out);
}

// round 3
// speedup vs baseline: 1.5971x; 1.5971x over previous
#include <cuda_runtime.h>

#define BB 32
#define SS 512
#define HH 256
#define NB 256
#define TT 4096   // MAX_LEN

#define NTOK (BB * SS)          // 16384 expand blocks
#define ZFRAMES 8               // frames per zerofill block
#define NZB (BB * (TT / ZFRAMES))  // 16384 zerofill blocks

__device__ int g_cum[BB * SS];

// searchsorted(linspace(vmin,vmax,NB), v, side='left'), clip [0, NB-1].
// Post-clip v <= b[NB-1] so the answer lies in [0, NB-1]: 8 exact iterations.
__device__ __forceinline__ int quantize_bin(float v, float vmin, float vmax) {
    v = fminf(fmaxf(v, vmin), vmax);
    float step = __fdiv_rn(__fsub_rn(vmax, vmin), (float)(NB - 1));
    int lo = 0, hi = NB - 1;
    #pragma unroll
    for (int it = 0; it < 8; ++it) {
        int mid = (lo + hi) >> 1;
        float b = __fadd_rn(__fmul_rn((float)mid, step), vmin);
        if (b >= v) hi = mid; else lo = mid + 1;
    }
    return lo;
}

// one block (512 thr) per batch row: warp-shuffle inclusive scan
__global__ void cumsum_kernel(const float* __restrict__ dur) {
    __shared__ int warp_tot[16];
    int b = blockIdx.x, i = threadIdx.x;
    int lane = i & 31, w = i >> 5;
    int d = max((int)rintf(dur[b * SS + i]), 1);   // jnp.round = half-to-even
    // warp inclusive scan
    int v = d;
    #pragma unroll
    for (int off = 1; off < 32; off <<= 1) {
        int u = __shfl_up_sync(0xffffffffu, v, off);
        if (lane >= off) v += u;
    }
    if (lane == 31) warp_tot[w] = v;
    __syncthreads();
    if (w == 0) {
        int t = (lane < 16) ? warp_tot[lane] : 0;
        #pragma unroll
        for (int off = 1; off < 16; off <<= 1) {
            int u = __shfl_up_sync(0xffffffffu, t, off);
            if (lane >= off) t += u;
        }
        if (lane < 16) warp_tot[lane] = t;
    }
    __syncthreads();
    int base = (w > 0) ? warp_tot[w - 1] : 0;
    g_cum[b * SS + i] = base + v;
}

// Fused expand + zerofill. 64 threads/block.
// blockIdx.x <  NTOK : token (b,s) — read row once, write it dur times.
// blockIdx.x >= NTOK : zerofill role — 8 frames of one batch, write zeros if t >= total.
__global__ void __launch_bounds__(64)
expand_kernel(const float* __restrict__ enc,
              const float* __restrict__ pitch,
              const float* __restrict__ energy,
              const float* __restrict__ ptab,
              const float* __restrict__ etab,
              float* __restrict__ out) {
    int lane = threadIdx.x;                 // 0..63 (one float4 of the H row)

    if (blockIdx.x < NTOK) {
        int row = blockIdx.x;               // b*SS + s
        int b = row >> 9;
        int s = row & (SS - 1);

        int end   = g_cum[row];
        int start = (s == 0) ? 0 : g_cum[row - 1];

        // every thread computes the bins (cheap, avoids a sync)
        int pb = quantize_bin(__ldg(pitch + row),  50.0f, 400.0f);
        int eb = quantize_bin(__ldg(energy + row),  0.0f,   1.0f);

        float4 a = ((const float4*)(enc  + (size_t)row * HH))[lane];
        float4 p = ((const float4*)(ptab + (size_t)pb  * HH))[lane];
        float4 q = ((const float4*)(etab + (size_t)eb  * HH))[lane];
        float4 r;
        r.x = a.x + p.x + q.x;
        r.y = a.y + p.y + q.y;
        r.z = a.z + p.z + q.z;
        r.w = a.w + p.w + q.w;

        float4* dst = (float4*)out + ((size_t)b * TT + start) * (HH / 4) + lane;
        for (int t = start; t < end; ++t) {
            *dst = r;
            dst += HH / 4;
        }
    } else {
        int zid = blockIdx.x - NTOK;        // [0, NZB)
        int b = zid >> 9;                   // 512 chunks per batch
        int t0 = (zid & 511) * ZFRAMES;
        int total = g_cum[b * SS + SS - 1];
        if (t0 + ZFRAMES <= total) return;  // fully covered by tokens

        float4 z = make_float4(0.f, 0.f, 0.f, 0.f);
        float4* base = (float4*)out + ((size_t)b * TT + t0) * (HH / 4) + lane;
        #pragma unroll
        for (int f = 0; f < ZFRAMES; ++f) {
            if (t0 + f >= total)
                base[f * (HH / 4)] = z;
        }
    }
}

extern "C" void kernel_launch(void* const* d_in, const int* in_sizes, int n_in,
                              void* d_out, int out_size) {
    const float* enc    = (const float*)d_in[0];
    const float* pitch  = (const float*)d_in[1];
    const float* energy = (const float*)d_in[2];
    const float* dur    = (const float*)d_in[3];
    const float* ptab   = (const float*)d_in[4];
    const float* etab   = (const float*)d_in[5];
    float* out = (float*)d_out;

    cumsum_kernel<<<BB, SS>>>(dur);
    expand_kernel<<<NTOK + NZB, 64>>>(enc, pitch, energy, ptab, etab, out);
}

// round 4
// speedup vs baseline: 1.8052x; 1.1303x over previous
#include <cuda_runtime.h>

#define BB 32
#define SS 512
#define HH 256
#define NB 256
#define TT 4096   // MAX_LEN

#define NTOK   (BB * SS)        // 16384 tokens
#define TOKG   2                // tokens per 64-lane group
#define GROUPS 4                // groups per 256-thread block
#define NTB    (NTOK / (TOKG * GROUPS))   // 2048 token blocks

#define ZF     32               // frames per zerofill block (4 groups x 8)
#define NZB    (BB * (TT / ZF)) // 4096 zerofill blocks

__device__ int g_cum[BB * SS];

// searchsorted(linspace(vmin,vmax,NB), v, side='left'), clip [0, NB-1].
// Post-clip v <= b[NB-1] so answer in [0, NB-1]: 8 exact iterations.
__device__ __forceinline__ int quantize_bin(float v, float vmin, float vmax) {
    v = fminf(fmaxf(v, vmin), vmax);
    float step = __fdiv_rn(__fsub_rn(vmax, vmin), (float)(NB - 1));
    int lo = 0, hi = NB - 1;
    #pragma unroll
    for (int it = 0; it < 8; ++it) {
        int mid = (lo + hi) >> 1;
        float b = __fadd_rn(__fmul_rn((float)mid, step), vmin);
        if (b >= v) hi = mid; else lo = mid + 1;
    }
    return lo;
}

// one block (512 thr) per batch row: warp-shuffle inclusive scan
__global__ void cumsum_kernel(const float* __restrict__ dur) {
    __shared__ int warp_tot[16];
    int b = blockIdx.x, i = threadIdx.x;
    int lane = i & 31, w = i >> 5;
    int d = max((int)rintf(dur[b * SS + i]), 1);   // jnp.round = half-to-even
    int v = d;
    #pragma unroll
    for (int off = 1; off < 32; off <<= 1) {
        int u = __shfl_up_sync(0xffffffffu, v, off);
        if (lane >= off) v += u;
    }
    if (lane == 31) warp_tot[w] = v;
    __syncthreads();
    if (w == 0) {
        int t = (lane < 16) ? warp_tot[lane] : 0;
        #pragma unroll
        for (int off = 1; off < 16; off <<= 1) {
            int u = __shfl_up_sync(0xffffffffu, t, off);
            if (lane >= off) t += u;
        }
        if (lane < 16) warp_tot[lane] = t;
    }
    __syncthreads();
    int base = (w > 0) ? warp_tot[w - 1] : 0;
    g_cum[b * SS + i] = base + v;
}

// Fused expand + zerofill, 256 threads/block.
//   blockIdx.x <  NTB : 4 groups x 2 tokens — read each row once, scatter dur copies.
//   blockIdx.x >= NTB : 4 groups x 8 frames — zero tail frames.
__global__ void __launch_bounds__(256)
expand_kernel(const float* __restrict__ enc,
              const float* __restrict__ pitch,
              const float* __restrict__ energy,
              const float* __restrict__ ptab,
              const float* __restrict__ etab,
              float* __restrict__ out) {
    int gid  = threadIdx.x >> 6;   // 0..3
    int lane = threadIdx.x & 63;   // float4 index within H row

    if (blockIdx.x < NTB) {
        int tok0 = (blockIdx.x * GROUPS + gid) * TOKG;   // consecutive, same batch
        int row0 = tok0, row1 = tok0 + 1;
        int b  = row0 >> 9;
        int s0 = row0 & (SS - 1);

        // ---- issue ALL independent global loads up front (MLP) ----
        float4 a0 = ((const float4*)(enc + (size_t)row0 * HH))[lane];
        float4 a1 = ((const float4*)(enc + (size_t)row1 * HH))[lane];
        float pv0 = __ldg(pitch  + row0);
        float pv1 = __ldg(pitch  + row1);
        float ev0 = __ldg(energy + row0);
        float ev1 = __ldg(energy + row1);
        int cm1 = (s0 == 0) ? 0 : __ldg(g_cum + row0 - 1);
        int c0  = __ldg(g_cum + row0);
        int c1  = __ldg(g_cum + row1);

        // ---- bins (both tokens interleaved by the compiler) ----
        int pb0 = quantize_bin(pv0, 50.0f, 400.0f);
        int pb1 = quantize_bin(pv1, 50.0f, 400.0f);
        int eb0 = quantize_bin(ev0,  0.0f,   1.0f);
        int eb1 = quantize_bin(ev1,  0.0f,   1.0f);

        float4 p0 = ((const float4*)(ptab + (size_t)pb0 * HH))[lane];
        float4 p1 = ((const float4*)(ptab + (size_t)pb1 * HH))[lane];
        float4 q0 = ((const float4*)(etab + (size_t)eb0 * HH))[lane];
        float4 q1 = ((const float4*)(etab + (size_t)eb1 * HH))[lane];

        float4 r0, r1;
        r0.x = a0.x + p0.x + q0.x;  r0.y = a0.y + p0.y + q0.y;
        r0.z = a0.z + p0.z + q0.z;  r0.w = a0.w + p0.w + q0.w;
        r1.x = a1.x + p1.x + q1.x;  r1.y = a1.y + p1.y + q1.y;
        r1.z = a1.z + p1.z + q1.z;  r1.w = a1.w + p1.w + q1.w;

        // ---- scatter (streaming stores; output never re-read) ----
        size_t fbase = (size_t)b * TT * (HH / 4) + lane;
        float4* o4 = (float4*)out;
        for (int t = cm1; t < c0; ++t)
            __stcs(o4 + fbase + (size_t)t * (HH / 4), r0);
        for (int t = c0; t < c1; ++t)
            __stcs(o4 + fbase + (size_t)t * (HH / 4), r1);
    } else {
        int zid = blockIdx.x - NTB;            // [0, NZB)
        int b   = zid >> 7;                    // 128 chunks per batch (4096/32)
        int t0  = (zid & 127) * ZF + gid * (ZF / GROUPS);
        int total = __ldg(g_cum + b * SS + SS - 1);
        if (t0 + ZF / GROUPS <= total) return;

        float4 z = make_float4(0.f, 0.f, 0.f, 0.f);
        float4* base = (float4*)out + ((size_t)b * TT + t0) * (HH / 4) + lane;
        #pragma unroll
        for (int f = 0; f < ZF / GROUPS; ++f) {
            if (t0 + f >= total)
                __stcs(base + f * (HH / 4), z);
        }
    }
}

extern "C" void kernel_launch(void* const* d_in, const int* in_sizes, int n_in,
                              void* d_out, int out_size) {
    const float* enc    = (const float*)d_in[0];
    const float* pitch  = (const float*)d_in[1];
    const float* energy = (const float*)d_in[2];
    const float* dur    = (const float*)d_in[3];
    const float* ptab   = (const float*)d_in[4];
    const float* etab   = (const float*)d_in[5];
    float* out = (float*)d_out;

    cumsum_kernel<<<BB, SS>>>(dur);
    expand_kernel<<<NTB + NZB, 256>>>(enc, pitch, energy, ptab, etab, out);
}